// round 5
// baseline (speedup 1.0000x reference)
#include <cuda_runtime.h>
#include <cuda_bf16.h>
#include <cstdint>

// Analytic collapse (validated, rel_err 2.3e-7):
//   z_q = -sin(vqc_weights[0][q]); only CNOT(7,0) survives the reference's
//   flip-axis bug => ev[0] = z0*z7, ev[w>=1] = z_w.
//   out[b, j] = b_out[j] + W_out[j,:] . ev   -- identical for every row b.
// R3 ncu: issue-bound. Costs were (a) 8 sinf per thread in ALL 262K threads,
// (b) 4.19M scalar STS filling the full 16.78MB into smem before TMA.
// R4: sinf in 8 threads/block only; replicate row just 4x in smem (8KB),
// then 4x cp.async.bulk of 8KB per block. TMA moves the bytes; SIMT issues
// ~25 instructions per thread.

#define ROWS_PER_BLK 16
#define REP 4                       // row copies held in smem
#define GROUPS (ROWS_PER_BLK / REP) // bulk stores per block

__global__ void qg_tma_bcast2_kernel(const float* __restrict__ vqc_w,   // [2,8]
                                     const float* __restrict__ W_out,   // [HID,8]
                                     const float* __restrict__ b_out,   // [HID]
                                     float* __restrict__ out,
                                     int HID, long long rows) {
    __shared__ float zsh[8];
    extern __shared__ float buf[];   // REP * HID floats (8 KB)
    const int tid = threadIdx.x;

    if (tid < 8) zsh[tid] = -sinf(vqc_w[tid]);
    __syncthreads();

    float ev[8];
#pragma unroll
    for (int w = 0; w < 8; ++w) ev[w] = zsh[w];
    ev[0] = zsh[0] * zsh[7];         // only CNOT(7,0) acts

    // r[j] = b_out[j] + W_out[j,:] . ev ; write REP copies.
    for (int j = tid; j < HID; j += blockDim.x) {
        const float4* w4 = reinterpret_cast<const float4*>(W_out + (long long)j * 8);
        float4 a = w4[0];
        float4 b = w4[1];
        float acc = b_out[j];
        acc += a.x * ev[0] + a.y * ev[1] + a.z * ev[2] + a.w * ev[3];
        acc += b.x * ev[4] + b.y * ev[5] + b.z * ev[6] + b.w * ev[7];
#pragma unroll
        for (int c = 0; c < REP; ++c)
            buf[c * HID + j] = acc;  // consecutive tids -> conflict-free
    }
    __syncthreads();

    const long long row0 = (long long)blockIdx.x * ROWS_PER_BLK;
    if (row0 >= rows) return;

    if (tid == 0) {
        // Order generic-proxy STS before async-proxy bulk reads.
        asm volatile("fence.proxy.async.shared::cta;" ::: "memory");
        uint32_t saddr;
        asm("{ .reg .u64 t; cvta.to.shared.u64 t, %1; cvt.u32.u64 %0, t; }"
            : "=r"(saddr) : "l"(buf));
        const uint32_t bytes = (uint32_t)((long long)REP * HID * sizeof(float));
#pragma unroll
        for (int g = 0; g < GROUPS; ++g) {
            long long r0 = row0 + (long long)g * REP;
            if (r0 >= rows) break;
            uint64_t gaddr = (uint64_t)(out + r0 * (long long)HID);
            asm volatile("cp.async.bulk.global.shared::cta.bulk_group [%0], [%1], %2;"
                         :: "l"(gaddr), "r"(saddr), "r"(bytes) : "memory");
        }
        asm volatile("cp.async.bulk.commit_group;" ::: "memory");
        // Do not exit with bulk stores in flight (source smem dies).
        asm volatile("cp.async.bulk.wait_group 0;" ::: "memory");
    }
}

extern "C" void kernel_launch(void* const* d_in, const int* in_sizes, int n_in,
                              void* d_out, int out_size) {
    // metadata order: x_t, h_prev, W_in, b_in, vqc_weights, W_out, b_out
    const float* vqc_w = (const float*)d_in[4];
    const float* W_out = (const float*)d_in[5];
    const float* b_out = (const float*)d_in[6];
    float* out = (float*)d_out;

    const int HID = in_sizes[6];                       // 512
    const long long rows = (long long)out_size / HID;  // 8192

    const int threads = 512;
    const int blocks = (int)((rows + ROWS_PER_BLK - 1) / ROWS_PER_BLK);  // 512
    const size_t smem = (size_t)REP * HID * sizeof(float);               // 8 KB

    qg_tma_bcast2_kernel<<<blocks, threads, smem>>>(vqc_w, W_out, b_out, out, HID, rows);
}